// round 9
// baseline (speedup 1.0000x reference)
#include <cuda_runtime.h>

// PLIF scan: x [B=16, T=16, C=128, H=32, W=32] fp32, scalar leak w.
//   mem = w*mem + x_t; spike = (mem >= 1); mem *= (1 - spike)
// out = spikes, same shape/dtype as x.
//
// FINAL (R1 recipe — best of 8 measured variants):
//   - 1 float4 lane per thread, 2048 CTAs x 256 threads.
//   - Plain LDG/STG: ptxas software-pipelines the 16 timestep loads to its
//     preferred depth at 31 regs -> occ ~80%, ~128KB of in-flight loads/SM.
//   - T-scan entirely in registers (4 independent FMA/select chains).
//   - 268MB mandatory traffic at 37.9us kernel time = 7.08 TB/s effective,
//     ~88% of spec on a 50/50 r/w mix = mixed-stream HBM3e ceiling.
// Falsified alternatives: __ldcs/__stcs (force 16-deep batching, regs 78,
// occ 30%), __stwt (neutral), LPT=2 any form (pipeline depth halving or
// drain), single-wave grids (cost > tail savings), TPB=128 (neutral),
// read/write burst phasing (turnaround not the limiter).

#define B_   16
#define T_   16
#define CHW_ 131072            // 128*32*32
#define CHW4 (CHW_ / 4)        // 32768 float4 per (b,t) plane
#define NV4  (B_ * CHW4)       // 524288 threads total

__global__ __launch_bounds__(256) void plif_kernel(
    const float4* __restrict__ x,
    const float*  __restrict__ wp,
    float4*       __restrict__ out)
{
    const int tid = blockIdx.x * blockDim.x + threadIdx.x;
    if (tid >= NV4) return;

    const float w = *wp;                     // scalar, L1-broadcast

    const int b = tid >> 15;                 // tid / CHW4
    const int s = tid & (CHW4 - 1);          // tid % CHW4
    const float4* xb = x   + (size_t)b * (T_ * CHW4) + s;
    float4*       ob = out + (size_t)b * (T_ * CHW4) + s;

    // Front-batch all 16 loads (independent addresses -> deep MLP;
    // ptxas pipelines to its preferred depth at 31 regs).
    float4 xs[T_];
    #pragma unroll
    for (int t = 0; t < T_; ++t)
        xs[t] = xb[t * CHW4];

    float m0 = 0.f, m1 = 0.f, m2 = 0.f, m3 = 0.f;

    #pragma unroll
    for (int t = 0; t < T_; ++t) {
        m0 = fmaf(w, m0, xs[t].x);
        m1 = fmaf(w, m1, xs[t].y);
        m2 = fmaf(w, m2, xs[t].z);
        m3 = fmaf(w, m3, xs[t].w);

        const float s0 = (m0 >= 1.0f) ? 1.0f : 0.0f;
        const float s1 = (m1 >= 1.0f) ? 1.0f : 0.0f;
        const float s2 = (m2 >= 1.0f) ? 1.0f : 0.0f;
        const float s3 = (m3 >= 1.0f) ? 1.0f : 0.0f;

        // mem *= (1 - spike)  ->  hard reset on spike
        m0 = (s0 != 0.0f) ? 0.0f : m0;
        m1 = (s1 != 0.0f) ? 0.0f : m1;
        m2 = (s2 != 0.0f) ? 0.0f : m2;
        m3 = (s3 != 0.0f) ? 0.0f : m3;

        float4 o; o.x = s0; o.y = s1; o.z = s2; o.w = s3;
        ob[t * CHW4] = o;
    }
}

extern "C" void kernel_launch(void* const* d_in, const int* in_sizes, int n_in,
                              void* d_out, int out_size)
{
    const float4* x  = (const float4*)d_in[0];
    const float*  wp = (const float*)d_in[1];
    float4* out = (float4*)d_out;

    const int threads = 256;
    const int blocks  = (NV4 + threads - 1) / threads;   // 2048
    plif_kernel<<<blocks, threads>>>(x, wp, out);
}

// round 10
// speedup vs baseline: 1.0276x; 1.0276x over previous
#include <cuda_runtime.h>
#include <cstdint>

// PLIF scan: x [B=16, T=16, C=128, H=32, W=32] fp32, scalar leak w.
//   mem = w*mem + x_t; spike = (mem >= 1); mem *= (1 - spike)
//
// Round 10: sm_100a 256-bit global accesses (ld/st.global.v8.f32).
// Each thread owns 8 consecutive floats per (b,t) plane; one LDG.256 +
// one STG.256 per timestep. Per warp: 1KB contiguous per instruction ->
// half the L1tex wavefronts / LSU dispatches / scoreboard slots per byte
// vs the float4 kernel. Geometry keeps R1's residency: TPB=128, 2048
// CTAs -> ~2048 threads/SM.

#define B_    16
#define T_    16
#define CHW_  131072                // 128*32*32 floats per (b,t) plane
#define CHW8  (CHW_ / 8)            // 16384 8-float lanes per plane
#define NV8   (B_ * CHW8)           // 262144 threads
#define TPB   128

struct f8 { float v[8]; };

__device__ __forceinline__ f8 ldg256(const float* p) {
    f8 r;
    asm("ld.global.v8.f32 {%0,%1,%2,%3,%4,%5,%6,%7}, [%8];"
        : "=f"(r.v[0]), "=f"(r.v[1]), "=f"(r.v[2]), "=f"(r.v[3]),
          "=f"(r.v[4]), "=f"(r.v[5]), "=f"(r.v[6]), "=f"(r.v[7])
        : "l"(p));
    return r;
}

__device__ __forceinline__ void stg256(float* p, const f8& r) {
    asm volatile("st.global.v8.f32 [%0], {%1,%2,%3,%4,%5,%6,%7,%8};"
        :: "l"(p),
           "f"(r.v[0]), "f"(r.v[1]), "f"(r.v[2]), "f"(r.v[3]),
           "f"(r.v[4]), "f"(r.v[5]), "f"(r.v[6]), "f"(r.v[7])
        : "memory");
}

__global__ __launch_bounds__(TPB) void plif_kernel(
    const float* __restrict__ x,
    const float* __restrict__ wp,
    float*       __restrict__ out)
{
    const int tid = blockIdx.x * blockDim.x + threadIdx.x;
    if (tid >= NV8) return;

    const float w = *wp;                      // scalar, L1-broadcast

    const int b = tid >> 14;                  // tid / CHW8
    const int s = tid & (CHW8 - 1);           // tid % CHW8
    const float* xb = x   + (size_t)b * (T_ * CHW_) + (size_t)s * 8;
    float*       ob = out + (size_t)b * (T_ * CHW_) + (size_t)s * 8;

    // 16 independent 256-bit loads; ptxas pipelines to its preferred depth.
    f8 xs[T_];
    #pragma unroll
    for (int t = 0; t < T_; ++t)
        xs[t] = ldg256(xb + (size_t)t * CHW_);

    float m[8];
    #pragma unroll
    for (int i = 0; i < 8; ++i) m[i] = 0.0f;

    #pragma unroll
    for (int t = 0; t < T_; ++t) {
        f8 o;
        #pragma unroll
        for (int i = 0; i < 8; ++i) {
            m[i] = fmaf(w, m[i], xs[t].v[i]);
            const float sp = (m[i] >= 1.0f) ? 1.0f : 0.0f;
            m[i] = (sp != 0.0f) ? 0.0f : m[i];
            o.v[i] = sp;
        }
        stg256(ob + (size_t)t * CHW_, o);
    }
}

extern "C" void kernel_launch(void* const* d_in, const int* in_sizes, int n_in,
                              void* d_out, int out_size)
{
    const float* x  = (const float*)d_in[0];
    const float* wp = (const float*)d_in[1];
    float* out = (float*)d_out;

    const int blocks = (NV8 + TPB - 1) / TPB;   // 2048
    plif_kernel<<<blocks, TPB>>>(x, wp, out);
}